// round 15
// baseline (speedup 1.0000x reference)
#include <cuda_runtime.h>
#include <cuda_fp16.h>
#include <cstdint>

#define TT 16384
#define HH 2048
#define FFD 8192
#define EE 8
#define RR 16

#define NC 64                    // f-chunk width
#define NSEG 4                   // FF segments (CTA-parallel)
#define NCHUNK_TOT (FFD / NC)            // 128
#define NCHUNK_SEG (NCHUNK_TOT / NSEG)   // 32
#define MT 128                   // token tile per CTA (k2/k3)

#define K1_TOK 64                // tokens per CTA (k1)
#define K1_KC  64                // K columns per chunk
#define XPAD   72                // smem row stride in halfs (144B): frag bank = lane

#define K3_COLS 512              // columns per k3 block

typedef unsigned long long u64;

// ---------------- scratch ------------------------------------------------------
__device__ float g_z1[TT * RR];                 // 1 MB
__device__ float g_z2p[NSEG * TT * RR];         // 4 MB (per-FF-segment partials)
__device__ float g_M[EE * RR * RR];             // per-expert 0.5*B1@A2^T
__device__ long long g_off[EE + 1];
__device__ int g_mbb[EE];                        // per-expert max ||B1col||^2 (float bits)
__device__ __half g_cb1[EE * NCHUNK_TOT * 1024];
__device__ __half g_ca2[EE * NCHUNK_TOT * 1024];
__device__ __half g_cb2[EE * (HH / 8) * 128];    // B2 fragment tiles, 512 KB

// ---------------- scalar helpers ----------------------------------------------
__device__ __forceinline__ u64 ffma2(u64 a, u64 b, u64 c) {
    u64 d;
    asm("fma.rn.f32x2 %0, %1, %2, %3;" : "=l"(d) : "l"(a), "l"(b), "l"(c));
    return d;
}
__device__ __forceinline__ u64 pack2(float x, float y) {
    u64 r;
    asm("mov.b64 %0, {%1, %2};" : "=l"(r) : "f"(x), "f"(y));
    return r;
}
__device__ __forceinline__ float2 unpack2(u64 v) {
    float2 r;
    asm("mov.b64 {%0, %1}, %2;" : "=f"(r.x), "=f"(r.y) : "l"(v));
    return r;
}

// exact gelu (A&S 7.1.26 erf) — slow paths / rare fallback
__device__ __forceinline__ float gelu_f(float x) {
    float ax = fabsf(x) * 0.7071067811865475f;
    float t  = __fdividef(1.0f, fmaf(0.3275911f, ax, 1.0f));
    float p  = fmaf(t, 1.061405429f, -1.453152027f);
    p = fmaf(p, t, 1.421413741f);
    p = fmaf(p, t, -0.284496736f);
    p = fmaf(p, t, 0.254829592f);
    p *= t;
    float ex = __expf(-ax * ax);
    float er = fmaf(-p, ex, 1.0f);
    er = copysignf(er, x);
    return 0.5f * x * (1.0f + er);
}

// G(x) = gelu(x)-0.5x = t*Q(t), t=x^2; degree-2 Q valid t<=0.5
#define GC0 0.3989422804014327f
#define GC1 (-0.06649038006690545f)
#define GC2 0.009973557010035818f

__device__ __forceinline__ int expert_of(int t) {
    int e = 0;
#pragma unroll
    for (int i = 1; i <= EE; i++)
        if ((long long)t >= g_off[i]) e = i;
    return e;
}

// m16n8k16 fp16 MMA, fp32 accum
__device__ __forceinline__ void mma16816(float* d, const uint32_t* a,
                                         const uint32_t* b, const float* c) {
    asm volatile(
        "mma.sync.aligned.m16n8k16.row.col.f32.f16.f16.f32 "
        "{%0,%1,%2,%3}, {%4,%5,%6,%7}, {%8,%9}, {%10,%11,%12,%13};"
        : "=f"(d[0]), "=f"(d[1]), "=f"(d[2]), "=f"(d[3])
        : "r"(a[0]), "r"(a[1]), "r"(a[2]), "r"(a[3]),
          "r"(b[0]), "r"(b[1]),
          "f"(c[0]), "f"(c[1]), "f"(c[2]), "f"(c[3]));
}
__device__ __forceinline__ uint32_t h2u(__half2 h) { return *(uint32_t*)&h; }

// ---------------- k_cvt: fp32 weights -> fp16 fragment tiles + B1 col-norm max -
__global__ __launch_bounds__(256) void k_cvt(const float* __restrict__ w1B,
                                             const float* __restrict__ w2A) {
    __shared__ float tb[RR][NC];
    __shared__ float ta[RR][NC];
    int e = blockIdx.x >> 7;
    int chunk = blockIdx.x & 127;
    int tid = threadIdx.x;
#pragma unroll
    for (int i = 0; i < 4; i++) {
        int idx = tid + i * 256;
        int r = idx >> 6, f = idx & 63;
        tb[r][f] = w1B[(size_t)(e * RR + r) * FFD + chunk * NC + f];
        ta[r][f] = w2A[(size_t)(e * RR + r) * FFD + chunk * NC + f];
    }
    __syncthreads();
    size_t base = (size_t)(e * NCHUNK_TOT + chunk) * 1024;
    {
        int frow = tid >> 2, c = tid & 3;
        __half2 h0 = __floats2half2_rn(tb[2 * c][frow], tb[2 * c + 1][frow]);
        __half2 h1 = __floats2half2_rn(tb[2 * c + 8][frow], tb[2 * c + 9][frow]);
        uint2 v; v.x = h2u(h0); v.y = h2u(h1);
        *(uint2*)&g_cb1[base + frow * 16 + c * 4] = v;
    }
    {
        int tile = tid >> 5, nr = (tid >> 2) & 7, c = tid & 3;
        int j = tile >> 2, s = tile & 3;
        int n = 8 * j + nr;
        __half2 h0 = __floats2half2_rn(ta[n][16 * s + 2 * c], ta[n][16 * s + 2 * c + 1]);
        __half2 h1 = __floats2half2_rn(ta[n][16 * s + 2 * c + 8], ta[n][16 * s + 2 * c + 9]);
        uint2 v; v.x = h2u(h0); v.y = h2u(h1);
        *(uint2*)&g_ca2[base + tile * 128 + nr * 16 + c * 4] = v;
    }
    if (tid < NC) {
        float s = 0.f;
#pragma unroll
        for (int r = 0; r < RR; r++) s = fmaf(tb[r][tid], tb[r][tid], s);
        atomicMax(&g_mbb[e], __float_as_int(s));
    }
}

// ---------------- k_cvt2: B2 fp32 -> fp16 fragment tiles -----------------------
// tile j (8 cols) block = 128 halfs: [nr 0..7][c 0..3][4 halfs k={2c,2c+1,2c+8,2c+9}]
__global__ __launch_bounds__(256) void k_cvt2(const float* __restrict__ w2B) {
    int e = blockIdx.x;
    int tid = threadIdx.x;
    for (int idx = tid; idx < RR * HH; idx += 256) {
        int r = idx >> 11;           // 0..15
        int col = idx & (HH - 1);
        float v = w2B[(size_t)(e * RR + r) * HH + col];
        int tile = col >> 3, nr = col & 7;
        int c, sub;
        if (r < 8) { c = r >> 1; sub = r & 1; }
        else       { c = (r - 8) >> 1; sub = 2 + (r & 1); }
        g_cb2[(size_t)e * (HH / 8) * 128 + tile * 128 + nr * 16 + c * 4 + sub] =
            __float2half_rn(v);
    }
}

// ---------------- k_lin: g_M + expert bounds -----------------------------------
__global__ __launch_bounds__(256) void k_lin(const float* __restrict__ w1B,
                                             const float* __restrict__ w2A,
                                             const void* __restrict__ tpe_raw) {
    if (blockIdx.x == 0 && threadIdx.x == 0) {
        const int* p32 = (const int*)tpe_raw;
        long long s32 = 0;
#pragma unroll
        for (int i = 0; i < EE; i++) s32 += (long long)p32[i];
        long long a = 0;
        g_off[0] = 0;
        if (s32 == (long long)TT) {
#pragma unroll
            for (int i = 0; i < EE; i++) { a += (long long)p32[i]; g_off[i + 1] = a; }
        } else {
            const long long* p64 = (const long long*)tpe_raw;
#pragma unroll
            for (int i = 0; i < EE; i++) { a += p64[i]; g_off[i + 1] = a; }
        }
    }
    __shared__ float red[256 * RR];
    int e  = blockIdx.x >> 4;
    int r1 = blockIdx.x & 15;
    const float* b1 = w1B + (size_t)(e * RR + r1) * FFD;
    const float* a2 = w2A + (size_t)e * RR * FFD;
    float acc[RR];
#pragma unroll
    for (int r = 0; r < RR; r++) acc[r] = 0.f;
    for (int f = threadIdx.x; f < FFD; f += 256) {
        float bv = b1[f];
#pragma unroll
        for (int r2 = 0; r2 < RR; r2++)
            acc[r2] = fmaf(bv, a2[(size_t)r2 * FFD + f], acc[r2]);
    }
#pragma unroll
    for (int r = 0; r < RR; r++) red[threadIdx.x * RR + r] = acc[r];
    __syncthreads();
    for (int off = 128; off > 0; off >>= 1) {
        if (threadIdx.x < off) {
#pragma unroll
            for (int r = 0; r < RR; r++)
                red[threadIdx.x * RR + r] += red[(threadIdx.x + off) * RR + r];
        }
        __syncthreads();
    }
    if (threadIdx.x < RR)
        g_M[(e * RR + r1) * RR + threadIdx.x] = 0.5f * red[threadIdx.x];
}

// ---------------- k1: z1 = x @ A1^T — warp MMA, 2 K-halves x 4 m-tiles ---------
__global__ __launch_bounds__(256) void k1_z1(const float* __restrict__ x,
                                             const float* __restrict__ w1A) {
    __shared__ __half xh[2][2][K1_TOK][XPAD];
    __shared__ __half wh[2][2][RR][XPAD];

    int tid  = threadIdx.x;
    int warp = tid >> 5, lane = tid & 31;
    int half = warp >> 2, mt = warp & 3;
    int lt   = tid & 127;
    int tok0 = blockIdx.x * K1_TOK;

    int e_first = expert_of(tok0);
    int e_last  = expert_of(tok0 + K1_TOK - 1);
    bool uni = (e_first == e_last);

    if (!uni || e_first >= EE) {
        if (tid < K1_TOK) {
            int token = tok0 + tid;
            int e = expert_of(token);
            float acc[RR];
#pragma unroll
            for (int r = 0; r < RR; r++) acc[r] = 0.f;
            if (e < EE) {
                const float* xrow = x + (size_t)token * HH;
                const float* arow = w1A + (size_t)e * RR * HH;
                for (int k = 0; k < HH; k++) {
                    float xv = xrow[k];
#pragma unroll
                    for (int r = 0; r < RR; r++)
                        acc[r] = fmaf(xv, __ldg(&arow[(size_t)r * HH + k]), acc[r]);
                }
            }
#pragma unroll
            for (int i = 0; i < 4; i++)
                *(float4*)&g_z1[token * RR + i * 4] =
                    make_float4(acc[i * 4], acc[i * 4 + 1], acc[i * 4 + 2], acc[i * 4 + 3]);
        }
        return;
    }

    const float* arow = w1A + (size_t)e_first * RR * HH;
    int kb = half * (HH / 2);

    float zacc[2][4];
#pragma unroll
    for (int j = 0; j < 2; j++)
#pragma unroll
        for (int q = 0; q < 4; q++) zacc[j][q] = 0.f;

    float4 px[8], pw[2];
#pragma unroll
    for (int i = 0; i < 8; i++) {
        int idx = lt + i * 128;
        int row = idx >> 4, c4 = idx & 15;
        px[i] = *(const float4*)&x[(size_t)(tok0 + row) * HH + kb + c4 * 4];
    }
#pragma unroll
    for (int i = 0; i < 2; i++) {
        int idx = lt + i * 128;
        int row = idx >> 4, c4 = idx & 15;
        pw[i] = *(const float4*)&arow[(size_t)row * HH + kb + c4 * 4];
    }

    int mrow = mt * 16 + (lane >> 2);
    int kcol = (lane & 3) * 2;
    const int NLOC = HH / 2 / K1_KC;

    for (int li = 0; li < NLOC; li++) {
        int buf = li & 1;
#pragma unroll
        for (int i = 0; i < 8; i++) {
            int idx = lt + i * 128;
            int row = idx >> 4, c4 = idx & 15;
            __half2 h0 = __floats2half2_rn(px[i].x, px[i].y);
            __half2 h1 = __floats2half2_rn(px[i].z, px[i].w);
            uint2 v; v.x = h2u(h0); v.y = h2u(h1);
            *(uint2*)&xh[half][buf][row][c4 * 4] = v;
        }
#pragma unroll
        for (int i = 0; i < 2; i++) {
            int idx = lt + i * 128;
            int row = idx >> 4, c4 = idx & 15;
            __half2 h0 = __floats2half2_rn(pw[i].x, pw[i].y);
            __half2 h1 = __floats2half2_rn(pw[i].z, pw[i].w);
            uint2 v; v.x = h2u(h0); v.y = h2u(h1);
            *(uint2*)&wh[half][buf][row][c4 * 4] = v;
        }
        __syncthreads();
        if (li + 1 < NLOC) {
            int kc = kb + (li + 1) * K1_KC;
#pragma unroll
            for (int i = 0; i < 8; i++) {
                int idx = lt + i * 128;
                int row = idx >> 4, c4 = idx & 15;
                px[i] = *(const float4*)&x[(size_t)(tok0 + row) * HH + kc + c4 * 4];
            }
#pragma unroll
            for (int i = 0; i < 2; i++) {
                int idx = lt + i * 128;
                int row = idx >> 4, c4 = idx & 15;
                pw[i] = *(const float4*)&arow[(size_t)row * HH + kc + c4 * 4];
            }
        }
#pragma unroll
        for (int kt = 0; kt < 4; kt++) {
            uint32_t a[4];
            a[0] = *(const uint32_t*)&xh[half][buf][mrow][kt * 16 + kcol];
            a[1] = *(const uint32_t*)&xh[half][buf][mrow + 8][kt * 16 + kcol];
            a[2] = *(const uint32_t*)&xh[half][buf][mrow][kt * 16 + kcol + 8];
            a[3] = *(const uint32_t*)&xh[half][buf][mrow + 8][kt * 16 + kcol + 8];
#pragma unroll
            for (int jn = 0; jn < 2; jn++) {
                uint32_t b[2];
                b[0] = *(const uint32_t*)&wh[half][buf][jn * 8 + (lane >> 2)][kt * 16 + kcol];
                b[1] = *(const uint32_t*)&wh[half][buf][jn * 8 + (lane >> 2)][kt * 16 + kcol + 8];
                mma16816(zacc[jn], a, b, zacc[jn]);
            }
        }
    }

    __syncthreads();
    float* red = (float*)wh;
    if (half == 1) {
#pragma unroll
        for (int jn = 0; jn < 2; jn++)
#pragma unroll
            for (int q = 0; q < 4; q++)
                red[(mt * 32 + lane) * 8 + jn * 4 + q] = zacc[jn][q];
    }
    __syncthreads();
    if (half == 0) {
        int t0 = tok0 + mrow, t1 = t0 + 8;
#pragma unroll
        for (int jn = 0; jn < 2; jn++) {
#pragma unroll
            for (int q = 0; q < 4; q++)
                zacc[jn][q] += red[(mt * 32 + lane) * 8 + jn * 4 + q];
            *(float2*)&g_z1[(size_t)t0 * RR + jn * 8 + kcol] =
                make_float2(zacc[jn][0], zacc[jn][1]);
            *(float2*)&g_z1[(size_t)t1 * RR + jn * 8 + kcol] =
                make_float2(zacc[jn][2], zacc[jn][3]);
        }
    }
}

// ---------------- k2: fused middle, 2 chunks/iter, hoisted guard ---------------
__global__ __launch_bounds__(256) void k2_mma(const float* __restrict__ w1B,
                                              const float* __restrict__ w2A) {
    __shared__ uint4 sb[4][128];
    __shared__ uint4 sa[4][128];
    __shared__ float sM[RR * RR];

    int tid  = threadIdx.x;
    int warp = tid >> 5, lane = tid & 31;
    int tok0 = blockIdx.x * MT;
    int seg  = blockIdx.y;
    int c0   = seg * NCHUNK_SEG;
    float* z2o = g_z2p + (size_t)seg * TT * RR;

    int e_first = expert_of(tok0);
    int e_last  = expert_of(tok0 + MT - 1);
    bool uni = (e_first == e_last);

    if (!uni) {
        if (tid < MT) {
            int token = tok0 + tid;
            int e = expert_of(token);
            float acc[RR];
#pragma unroll
            for (int r = 0; r < RR; r++) acc[r] = 0.f;
            if (e < EE) {
                float zr[RR];
#pragma unroll
                for (int r = 0; r < RR; r++) zr[r] = g_z1[token * RR + r];
                const float* b1 = w1B + (size_t)e * RR * FFD;
                const float* a2 = w2A + (size_t)e * RR * FFD;
                int f0 = c0 * NC, f1 = f0 + NCHUNK_SEG * NC;
                for (int f = f0; f < f1; f++) {
                    float hv = 0.f;
#pragma unroll
                    for (int r = 0; r < RR; r++)
                        hv = fmaf(zr[r], b1[(size_t)r * FFD + f], hv);
                    float h = gelu_f(hv);
#pragma unroll
                    for (int r = 0; r < RR; r++)
                        acc[r] = fmaf(h, a2[(size_t)r * FFD + f], acc[r]);
                }
            }
#pragma unroll
            for (int r = 0; r < RR; r++) z2o[token * RR + r] = acc[r];
        }
        return;
    }
    if (e_first >= EE) {
        if (tid < MT) {
#pragma unroll
            for (int i = 0; i < 4; i++)
                *(float4*)&z2o[(size_t)(tok0 + tid) * RR + i * 4] =
                    make_float4(0.f, 0.f, 0.f, 0.f);
        }
        return;
    }

    int e = e_first;
    const uint4* cb = (const uint4*)&g_cb1[(size_t)(e * NCHUNK_TOT + c0) * 1024];
    const uint4* ca = (const uint4*)&g_ca2[(size_t)(e * NCHUNK_TOT + c0) * 1024];

    sM[tid] = g_M[e * 256 + tid];

    int mrow = warp * 16 + (lane >> 2);
    int kcol = (lane & 3) * 2;
    uint32_t za[4];
    {
        float2 v00 = *(const float2*)&g_z1[(tok0 + mrow) * RR + kcol];
        float2 v10 = *(const float2*)&g_z1[(tok0 + mrow + 8) * RR + kcol];
        float2 v01 = *(const float2*)&g_z1[(tok0 + mrow) * RR + kcol + 8];
        float2 v11 = *(const float2*)&g_z1[(tok0 + mrow + 8) * RR + kcol + 8];
        za[0] = h2u(__floats2half2_rn(v00.x, v00.y));
        za[1] = h2u(__floats2half2_rn(v10.x, v10.y));
        za[2] = h2u(__floats2half2_rn(v01.x, v01.y));
        za[3] = h2u(__floats2half2_rn(v11.x, v11.y));
    }

    int pred = 1;
    if (tid < MT) {
        float nz = 0.f;
#pragma unroll
        for (int i = 0; i < 4; i++) {
            float4 v = *(const float4*)&g_z1[(size_t)(tok0 + tid) * RR + i * 4];
            nz = fmaf(v.x, v.x, nz); nz = fmaf(v.y, v.y, nz);
            nz = fmaf(v.z, v.z, nz); nz = fmaf(v.w, v.w, nz);
        }
        float mb2 = __int_as_float(g_mbb[e]);
        pred = (nz * mb2 <= 0.49f) ? 1 : 0;
    }
    int allok = __syncthreads_and(pred);

    if (tid < 128) { sb[0][tid] = cb[tid]; sb[1][tid] = cb[128 + tid]; }
    else { sa[0][tid - 128] = ca[tid - 128]; sa[1][tid - 128] = ca[128 + tid - 128]; }
    __syncthreads();

    float zacc[2][4];
#pragma unroll
    for (int j = 0; j < 2; j++)
#pragma unroll
        for (int q = 0; q < 4; q++) zacc[j][q] = 0.f;

    uint32_t foff = (uint32_t)(lane >> 2) * 32 + (uint32_t)(lane & 3) * 8;
    const u64 gc2p = pack2(GC2, GC2);
    const u64 gc1p = pack2(GC1, GC1);
    const u64 gc0p = pack2(GC0, GC0);

    for (int ci = 0; ci < NCHUNK_SEG; ci += 2) {
        int pair = (ci >> 1) & 1;
        bool have_next = (ci + 2 < NCHUNK_SEG);

        uint4 pf0, pf1;
        if (have_next) {
            if (tid < 128) {
                pf0 = cb[(ci + 2) * 128 + tid];
                pf1 = cb[(ci + 3) * 128 + tid];
            } else {
                pf0 = ca[(ci + 2) * 128 + tid - 128];
                pf1 = ca[(ci + 3) * 128 + tid - 128];
            }
        }

#pragma unroll
        for (int h = 0; h < 2; h++) {
            const char* sbp = (const char*)&sb[2 * pair + h][0];
            const char* sap = (const char*)&sa[2 * pair + h][0];

            float c1[8][4];
#pragma unroll
            for (int j = 0; j < 8; j++) {
                uint2 bf = *(const uint2*)(sbp + j * 256 + foff);
                float zero4[4] = {0.f, 0.f, 0.f, 0.f};
                mma16816(c1[j], za, (const uint32_t*)&bf, zero4);
            }

            uint32_t ga[4][4];
#pragma unroll
            for (int j = 0; j < 8; j++) {
#pragma unroll
                for (int q = 0; q < 2; q++) {
                    float x0 = c1[j][2 * q], x1 = c1[j][2 * q + 1];
                    u64 xv = pack2(x0, x1);
                    u64 tv = ffma2(xv, xv, 0ull);
                    u64 qv = ffma2(gc2p, tv, gc1p);
                    qv = ffma2(qv, tv, gc0p);
                    u64 gv = ffma2(tv, qv, 0ull);
                    float2 gf = unpack2(gv);
                    ga[j >> 1][(j & 1) * 2 + q] = h2u(__floats2half2_rn(gf.x, gf.y));
                }
            }
            if (!allok) {
                float tmax = 0.f;
#pragma unroll
                for (int j = 0; j < 8; j++)
#pragma unroll
                    for (int q = 0; q < 4; q++)
                        tmax = fmaxf(tmax, c1[j][q] * c1[j][q]);
                if (tmax > 0.5f) {
#pragma unroll
                    for (int j = 0; j < 8; j++) {
#pragma unroll
                        for (int q = 0; q < 2; q++) {
                            float x0 = c1[j][2 * q], x1 = c1[j][2 * q + 1];
                            float g0 = gelu_f(x0) - 0.5f * x0;
                            float g1 = gelu_f(x1) - 0.5f * x1;
                            ga[j >> 1][(j & 1) * 2 + q] = h2u(__floats2half2_rn(g0, g1));
                        }
                    }
                }
            }

#pragma unroll
            for (int j = 0; j < 2; j++) {
#pragma unroll
                for (int s = 0; s < 4; s++) {
                    uint2 bf = *(const uint2*)(sap + (j * 4 + s) * 256 + foff);
                    mma16816(zacc[j], ga[s], (const uint32_t*)&bf, zacc[j]);
                }
            }
        }

        if (have_next) {
            int op = 2 * (pair ^ 1);
            if (tid < 128) { sb[op][tid] = pf0; sb[op + 1][tid] = pf1; }
            else { sa[op][tid - 128] = pf0; sa[op + 1][tid - 128] = pf1; }
        }
        __syncthreads();
    }

    {
        int t0 = tok0 + mrow, t1 = t0 + 8;
#pragma unroll
        for (int j = 0; j < 2; j++) {
            u64 accq[2];
#pragma unroll
            for (int q = 0; q < 2; q++)
                accq[q] = pack2(zacc[j][q], zacc[j][q + 2]);
            if (seg == 0) {
                float z1a[RR], z1b[RR];
#pragma unroll
                for (int i = 0; i < 4; i++) {
                    float4 v = *(const float4*)&g_z1[(size_t)t0 * RR + i * 4];
                    float4 w = *(const float4*)&g_z1[(size_t)t1 * RR + i * 4];
                    z1a[i * 4 + 0] = v.x; z1a[i * 4 + 1] = v.y;
                    z1a[i * 4 + 2] = v.z; z1a[i * 4 + 3] = v.w;
                    z1b[i * 4 + 0] = w.x; z1b[i * 4 + 1] = w.y;
                    z1b[i * 4 + 2] = w.z; z1b[i * 4 + 3] = w.w;
                }
#pragma unroll
                for (int q = 0; q < 2; q++) {
                    int r2 = 8 * j + kcol + q;
                    u64 acc = accq[q];
#pragma unroll
                    for (int r1 = 0; r1 < RR; r1++) {
                        float m = sM[r1 * RR + r2];
                        acc = ffma2(pack2(z1a[r1], z1b[r1]), pack2(m, m), acc);
                    }
                    accq[q] = acc;
                }
            }
            float2 a0 = unpack2(accq[0]), a1 = unpack2(accq[1]);
            *(float2*)&z2o[(size_t)t0 * RR + 8 * j + kcol] = make_float2(a0.x, a1.x);
            *(float2*)&z2o[(size_t)t1 * RR + 8 * j + kcol] = make_float2(a0.y, a1.y);
        }
    }
}

// ---------------- k3: out = (sum_seg z2p) @ B2 via warp MMA --------------------
// block: 128 tokens x 512 cols, 256 threads (8 warps x 16 tokens).
__global__ __launch_bounds__(256) void k3_out(const float* __restrict__ w2B,
                                              float* __restrict__ out) {
    __shared__ uint4 sB[K3_COLS / 8 * 16];      // 64 tiles x 256B = 16 KB

    int tid  = threadIdx.x;
    int warp = tid >> 5, lane = tid & 31;
    int tok0 = blockIdx.x * MT;
    int col0 = blockIdx.y * K3_COLS;

    int e_first = expert_of(tok0);
    int e_last  = expert_of(tok0 + MT - 1);
    bool uni = (e_first == e_last);

    if (!uni) {
        // slow path: per-token fp32 over this block's cols
        if (tid < MT) {
            int token = tok0 + tid;
            int e = expert_of(token);
            if (e < EE) {
                float zr[RR];
#pragma unroll
                for (int r = 0; r < RR; r++) {
                    float s = 0.f;
#pragma unroll
                    for (int g = 0; g < NSEG; g++)
                        s += g_z2p[(size_t)g * TT * RR + (size_t)token * RR + r];
                    zr[r] = s;
                }
                for (int c = col0; c < col0 + K3_COLS; c++) {
                    float a = 0.f;
#pragma unroll
                    for (int r = 0; r < RR; r++)
                        a = fmaf(zr[r], w2B[(size_t)(e * RR + r) * HH + c], a);
                    out[(size_t)token * HH + c] = a;
                }
            } else {
                for (int c = col0; c < col0 + K3_COLS; c++)
                    out[(size_t)token * HH + c] = 0.f;
            }
        }
        return;
    }
    if (e_first >= EE) {
        // zero this block's region
        for (int i = tid; i < MT * (K3_COLS / 4); i += 256) {
            int row = i / (K3_COLS / 4), c4 = i % (K3_COLS / 4);
            *(float4*)&out[(size_t)(tok0 + row) * HH + col0 + c4 * 4] =
                make_float4(0.f, 0.f, 0.f, 0.f);
        }
        return;
    }

    int e = e_first;
    // stage B2 tiles (64 tiles x 16 uint4)
    {
        const uint4* src = (const uint4*)&g_cb2[(size_t)e * (HH / 8) * 128 +
                                                (size_t)(col0 / 8) * 128];
#pragma unroll
        for (int i = 0; i < 4; i++) sB[tid + i * 256] = src[tid + i * 256];
    }

    // A-frag: z2 = sum of 4 segment partials, cvt fp16
    int mrow = warp * 16 + (lane >> 2);
    int kcol = (lane & 3) * 2;
    uint32_t za[4];
    {
        int t0 = tok0 + mrow, t1 = t0 + 8;
        float2 s00 = make_float2(0.f, 0.f), s10 = s00, s01 = s00, s11 = s00;
#pragma unroll
        for (int g = 0; g < NSEG; g++) {
            const float* base = g_z2p + (size_t)g * TT * RR;
            float2 v00 = *(const float2*)&base[(size_t)t0 * RR + kcol];
            float2 v10 = *(const float2*)&base[(size_t)t1 * RR + kcol];
            float2 v01 = *(const float2*)&base[(size_t)t0 * RR + kcol + 8];
            float2 v11 = *(const float2*)&base[(size_t)t1 * RR + kcol + 8];
            s00.x += v00.x; s00.y += v00.y;
            s10.x += v10.x; s10.y += v10.y;
            s01.x += v01.x; s01.y += v01.y;
            s11.x += v11.x; s11.y += v11.y;
        }
        za[0] = h2u(__floats2half2_rn(s00.x, s00.y));
        za[1] = h2u(__floats2half2_rn(s10.x, s10.y));
        za[2] = h2u(__floats2half2_rn(s01.x, s01.y));
        za[3] = h2u(__floats2half2_rn(s11.x, s11.y));
    }
    __syncthreads();

    const char* sbp = (const char*)sB;
    uint32_t foff = (uint32_t)(lane >> 2) * 32 + (uint32_t)(lane & 3) * 8;
    int t0 = tok0 + mrow, t1 = t0 + 8;
    int colb = col0 + (lane & 3) * 2;

#pragma unroll 4
    for (int j = 0; j < K3_COLS / 8; j++) {
        uint2 bf = *(const uint2*)(sbp + j * 256 + foff);
        float c[4];
        float zero4[4] = {0.f, 0.f, 0.f, 0.f};
        mma16816(c, za, (const uint32_t*)&bf, zero4);
        int col = colb + j * 8;
        *(float2*)&out[(size_t)t0 * HH + col] = make_float2(c[0], c[1]);
        *(float2*)&out[(size_t)t1 * HH + col] = make_float2(c[2], c[3]);
    }
}

// ---------------- launch --------------------------------------------------------
extern "C" void kernel_launch(void* const* d_in, const int* in_sizes, int n_in,
                              void* d_out, int out_size) {
    const float* x   = (const float*)d_in[0];
    const void*  tpe = (const void*)d_in[1];
    const float* w1A = (const float*)d_in[2];
    const float* w1B = (const float*)d_in[3];
    const float* w2A = (const float*)d_in[4];
    const float* w2B = (const float*)d_in[5];
    float* out = (float*)d_out;

    k_cvt<<<EE * NCHUNK_TOT, 256>>>(w1B, w2A);

    k_cvt2<<<EE, 256>>>(w2B);

    k_lin<<<EE * RR, 256>>>(w1B, w2A, tpe);   // also computes g_off (block 0)

    k1_z1<<<TT / K1_TOK, 256>>>(x, w1A);

    dim3 g2(TT / MT, NSEG);
    k2_mma<<<g2, 256>>>(w1B, w2A);

    dim3 g3(TT / MT, HH / K3_COLS);
    k3_out<<<g3, 256>>>(w2B, out);
}

// round 16
// speedup vs baseline: 1.1831x; 1.1831x over previous
#include <cuda_runtime.h>
#include <cuda_fp16.h>
#include <cstdint>

#define TT 16384
#define HH 2048
#define FFD 8192
#define EE 8
#define RR 16

#define NC 64                    // f-chunk width
#define NSEG 4                   // FF segments (CTA-parallel)
#define NCHUNK_TOT (FFD / NC)            // 128
#define NCHUNK_SEG (NCHUNK_TOT / NSEG)   // 32
#define MT 128                   // token tile per CTA (k2)

#define K1_TOK 64                // tokens per CTA (k1)
#define K1_KC  64                // K columns per chunk
#define XPAD   72                // smem row stride in halfs (144B): frag bank = lane

typedef unsigned long long u64;

// ---------------- scratch ------------------------------------------------------
__device__ float g_z1[TT * RR];                 // 1 MB
__device__ float g_z2p[NSEG * TT * RR];         // 4 MB (per-FF-segment partials)
__device__ float g_M[EE * RR * RR];             // per-expert 0.5*B1@A2^T
__device__ long long g_off[EE + 1];
__device__ int g_mbb[EE];                        // per-expert max ||B1col||^2 (float bits)
__device__ __half g_cb1[EE * NCHUNK_TOT * 1024];
__device__ __half g_ca2[EE * NCHUNK_TOT * 1024];

// ---------------- scalar helpers ----------------------------------------------
__device__ __forceinline__ u64 ffma2(u64 a, u64 b, u64 c) {
    u64 d;
    asm("fma.rn.f32x2 %0, %1, %2, %3;" : "=l"(d) : "l"(a), "l"(b), "l"(c));
    return d;
}
__device__ __forceinline__ u64 pack2(float x, float y) {
    u64 r;
    asm("mov.b64 %0, {%1, %2};" : "=l"(r) : "f"(x), "f"(y));
    return r;
}
__device__ __forceinline__ float2 unpack2(u64 v) {
    float2 r;
    asm("mov.b64 {%0, %1}, %2;" : "=f"(r.x), "=f"(r.y) : "l"(v));
    return r;
}

// exact gelu (A&S 7.1.26 erf) — slow paths / rare fallback
__device__ __forceinline__ float gelu_f(float x) {
    float ax = fabsf(x) * 0.7071067811865475f;
    float t  = __fdividef(1.0f, fmaf(0.3275911f, ax, 1.0f));
    float p  = fmaf(t, 1.061405429f, -1.453152027f);
    p = fmaf(p, t, 1.421413741f);
    p = fmaf(p, t, -0.284496736f);
    p = fmaf(p, t, 0.254829592f);
    p *= t;
    float ex = __expf(-ax * ax);
    float er = fmaf(-p, ex, 1.0f);
    er = copysignf(er, x);
    return 0.5f * x * (1.0f + er);
}

// G(x) = gelu(x)-0.5x = t*Q(t), t=x^2; degree-2 Q valid t<=0.5
#define GC0 0.3989422804014327f
#define GC1 (-0.06649038006690545f)
#define GC2 0.009973557010035818f

__device__ __forceinline__ int expert_of(int t) {
    int e = 0;
#pragma unroll
    for (int i = 1; i <= EE; i++)
        if ((long long)t >= g_off[i]) e = i;
    return e;
}

// m16n8k16 fp16 MMA, fp32 accum (baseline PTX — legal on plain sm_103)
__device__ __forceinline__ void mma16816(float* d, const uint32_t* a,
                                         const uint32_t* b, const float* c) {
    asm volatile(
        "mma.sync.aligned.m16n8k16.row.col.f32.f16.f16.f32 "
        "{%0,%1,%2,%3}, {%4,%5,%6,%7}, {%8,%9}, {%10,%11,%12,%13};"
        : "=f"(d[0]), "=f"(d[1]), "=f"(d[2]), "=f"(d[3])
        : "r"(a[0]), "r"(a[1]), "r"(a[2]), "r"(a[3]),
          "r"(b[0]), "r"(b[1]),
          "f"(c[0]), "f"(c[1]), "f"(c[2]), "f"(c[3]));
}
__device__ __forceinline__ uint32_t h2u(__half2 h) { return *(uint32_t*)&h; }

// ---------------- k_prep: weight cvt (blocks 0..1023) + g_M/g_off (1024..1151) -
__global__ __launch_bounds__(256) void k_prep(const float* __restrict__ w1B,
                                              const float* __restrict__ w2A,
                                              const void* __restrict__ tpe_raw) {
    __shared__ float tb[RR][NC];
    __shared__ float ta[RR][NC];
    __shared__ float red[256 * RR];
    int bid = blockIdx.x;
    int tid = threadIdx.x;

    if (bid < EE * NCHUNK_TOT) {
        // ---- cvt path: fp32 weights -> fp16 fragment tiles + B1 col-norm max --
        int e = bid >> 7;
        int chunk = bid & 127;
#pragma unroll
        for (int i = 0; i < 4; i++) {
            int idx = tid + i * 256;
            int r = idx >> 6, f = idx & 63;
            tb[r][f] = w1B[(size_t)(e * RR + r) * FFD + chunk * NC + f];
            ta[r][f] = w2A[(size_t)(e * RR + r) * FFD + chunk * NC + f];
        }
        __syncthreads();
        size_t base = (size_t)(e * NCHUNK_TOT + chunk) * 1024;
        {
            int frow = tid >> 2, c = tid & 3;
            __half2 h0 = __floats2half2_rn(tb[2 * c][frow], tb[2 * c + 1][frow]);
            __half2 h1 = __floats2half2_rn(tb[2 * c + 8][frow], tb[2 * c + 9][frow]);
            uint2 v; v.x = h2u(h0); v.y = h2u(h1);
            *(uint2*)&g_cb1[base + frow * 16 + c * 4] = v;
        }
        {
            int tile = tid >> 5, nr = (tid >> 2) & 7, c = tid & 3;
            int j = tile >> 2, s = tile & 3;
            int n = 8 * j + nr;
            __half2 h0 = __floats2half2_rn(ta[n][16 * s + 2 * c], ta[n][16 * s + 2 * c + 1]);
            __half2 h1 = __floats2half2_rn(ta[n][16 * s + 2 * c + 8], ta[n][16 * s + 2 * c + 9]);
            uint2 v; v.x = h2u(h0); v.y = h2u(h1);
            *(uint2*)&g_ca2[base + tile * 128 + nr * 16 + c * 4] = v;
        }
        if (tid < NC) {
            float s = 0.f;
#pragma unroll
            for (int r = 0; r < RR; r++) s = fmaf(tb[r][tid], tb[r][tid], s);
            atomicMax(&g_mbb[e], __float_as_int(s));
        }
        return;
    }

    // ---- lin path: g_M[e] = 0.5*B1@A2^T + expert bounds ----
    int bid2 = bid - EE * NCHUNK_TOT;
    if (bid2 == 0 && tid == 0) {
        const int* p32 = (const int*)tpe_raw;
        long long s32 = 0;
#pragma unroll
        for (int i = 0; i < EE; i++) s32 += (long long)p32[i];
        long long a = 0;
        g_off[0] = 0;
        if (s32 == (long long)TT) {
#pragma unroll
            for (int i = 0; i < EE; i++) { a += (long long)p32[i]; g_off[i + 1] = a; }
        } else {
            const long long* p64 = (const long long*)tpe_raw;
#pragma unroll
            for (int i = 0; i < EE; i++) { a += p64[i]; g_off[i + 1] = a; }
        }
    }
    int e  = bid2 >> 4;
    int r1 = bid2 & 15;
    const float* b1 = w1B + (size_t)(e * RR + r1) * FFD;
    const float* a2 = w2A + (size_t)e * RR * FFD;
    float acc[RR];
#pragma unroll
    for (int r = 0; r < RR; r++) acc[r] = 0.f;
    for (int f = tid; f < FFD; f += 256) {
        float bv = b1[f];
#pragma unroll
        for (int r2 = 0; r2 < RR; r2++)
            acc[r2] = fmaf(bv, a2[(size_t)r2 * FFD + f], acc[r2]);
    }
#pragma unroll
    for (int r = 0; r < RR; r++) red[tid * RR + r] = acc[r];
    __syncthreads();
    for (int off = 128; off > 0; off >>= 1) {
        if (tid < off) {
#pragma unroll
            for (int r = 0; r < RR; r++)
                red[tid * RR + r] += red[(tid + off) * RR + r];
        }
        __syncthreads();
    }
    if (tid < RR)
        g_M[(e * RR + r1) * RR + tid] = 0.5f * red[tid];
}

// ---------------- k1: z1 = x @ A1^T — warp MMA, 2 K-halves x 4 m-tiles ---------
__global__ __launch_bounds__(256) void k1_z1(const float* __restrict__ x,
                                             const float* __restrict__ w1A) {
    __shared__ __half xh[2][2][K1_TOK][XPAD];
    __shared__ __half wh[2][2][RR][XPAD];

    int tid  = threadIdx.x;
    int warp = tid >> 5, lane = tid & 31;
    int half = warp >> 2, mt = warp & 3;
    int lt   = tid & 127;
    int tok0 = blockIdx.x * K1_TOK;

    int e_first = expert_of(tok0);
    int e_last  = expert_of(tok0 + K1_TOK - 1);
    bool uni = (e_first == e_last);

    if (!uni || e_first >= EE) {
        if (tid < K1_TOK) {
            int token = tok0 + tid;
            int e = expert_of(token);
            float acc[RR];
#pragma unroll
            for (int r = 0; r < RR; r++) acc[r] = 0.f;
            if (e < EE) {
                const float* xrow = x + (size_t)token * HH;
                const float* arow = w1A + (size_t)e * RR * HH;
                for (int k = 0; k < HH; k++) {
                    float xv = xrow[k];
#pragma unroll
                    for (int r = 0; r < RR; r++)
                        acc[r] = fmaf(xv, __ldg(&arow[(size_t)r * HH + k]), acc[r]);
                }
            }
#pragma unroll
            for (int i = 0; i < 4; i++)
                *(float4*)&g_z1[token * RR + i * 4] =
                    make_float4(acc[i * 4], acc[i * 4 + 1], acc[i * 4 + 2], acc[i * 4 + 3]);
        }
        return;
    }

    const float* arow = w1A + (size_t)e_first * RR * HH;
    int kb = half * (HH / 2);

    float zacc[2][4];
#pragma unroll
    for (int j = 0; j < 2; j++)
#pragma unroll
        for (int q = 0; q < 4; q++) zacc[j][q] = 0.f;

    float4 px[8], pw[2];
#pragma unroll
    for (int i = 0; i < 8; i++) {
        int idx = lt + i * 128;
        int row = idx >> 4, c4 = idx & 15;
        px[i] = *(const float4*)&x[(size_t)(tok0 + row) * HH + kb + c4 * 4];
    }
#pragma unroll
    for (int i = 0; i < 2; i++) {
        int idx = lt + i * 128;
        int row = idx >> 4, c4 = idx & 15;
        pw[i] = *(const float4*)&arow[(size_t)row * HH + kb + c4 * 4];
    }

    int mrow = mt * 16 + (lane >> 2);
    int kcol = (lane & 3) * 2;
    const int NLOC = HH / 2 / K1_KC;

    for (int li = 0; li < NLOC; li++) {
        int buf = li & 1;
#pragma unroll
        for (int i = 0; i < 8; i++) {
            int idx = lt + i * 128;
            int row = idx >> 4, c4 = idx & 15;
            __half2 h0 = __floats2half2_rn(px[i].x, px[i].y);
            __half2 h1 = __floats2half2_rn(px[i].z, px[i].w);
            uint2 v; v.x = h2u(h0); v.y = h2u(h1);
            *(uint2*)&xh[half][buf][row][c4 * 4] = v;
        }
#pragma unroll
        for (int i = 0; i < 2; i++) {
            int idx = lt + i * 128;
            int row = idx >> 4, c4 = idx & 15;
            __half2 h0 = __floats2half2_rn(pw[i].x, pw[i].y);
            __half2 h1 = __floats2half2_rn(pw[i].z, pw[i].w);
            uint2 v; v.x = h2u(h0); v.y = h2u(h1);
            *(uint2*)&wh[half][buf][row][c4 * 4] = v;
        }
        __syncthreads();
        if (li + 1 < NLOC) {
            int kc = kb + (li + 1) * K1_KC;
#pragma unroll
            for (int i = 0; i < 8; i++) {
                int idx = lt + i * 128;
                int row = idx >> 4, c4 = idx & 15;
                px[i] = *(const float4*)&x[(size_t)(tok0 + row) * HH + kc + c4 * 4];
            }
#pragma unroll
            for (int i = 0; i < 2; i++) {
                int idx = lt + i * 128;
                int row = idx >> 4, c4 = idx & 15;
                pw[i] = *(const float4*)&arow[(size_t)row * HH + kc + c4 * 4];
            }
        }
#pragma unroll
        for (int kt = 0; kt < 4; kt++) {
            uint32_t a[4];
            a[0] = *(const uint32_t*)&xh[half][buf][mrow][kt * 16 + kcol];
            a[1] = *(const uint32_t*)&xh[half][buf][mrow + 8][kt * 16 + kcol];
            a[2] = *(const uint32_t*)&xh[half][buf][mrow][kt * 16 + kcol + 8];
            a[3] = *(const uint32_t*)&xh[half][buf][mrow + 8][kt * 16 + kcol + 8];
#pragma unroll
            for (int jn = 0; jn < 2; jn++) {
                uint32_t b[2];
                b[0] = *(const uint32_t*)&wh[half][buf][jn * 8 + (lane >> 2)][kt * 16 + kcol];
                b[1] = *(const uint32_t*)&wh[half][buf][jn * 8 + (lane >> 2)][kt * 16 + kcol + 8];
                mma16816(zacc[jn], a, b, zacc[jn]);
            }
        }
    }

    __syncthreads();
    float* red = (float*)wh;
    if (half == 1) {
#pragma unroll
        for (int jn = 0; jn < 2; jn++)
#pragma unroll
            for (int q = 0; q < 4; q++)
                red[(mt * 32 + lane) * 8 + jn * 4 + q] = zacc[jn][q];
    }
    __syncthreads();
    if (half == 0) {
        int t0 = tok0 + mrow, t1 = t0 + 8;
#pragma unroll
        for (int jn = 0; jn < 2; jn++) {
#pragma unroll
            for (int q = 0; q < 4; q++)
                zacc[jn][q] += red[(mt * 32 + lane) * 8 + jn * 4 + q];
            *(float2*)&g_z1[(size_t)t0 * RR + jn * 8 + kcol] =
                make_float2(zacc[jn][0], zacc[jn][1]);
            *(float2*)&g_z1[(size_t)t1 * RR + jn * 8 + kcol] =
                make_float2(zacc[jn][2], zacc[jn][3]);
        }
    }
}

// ---------------- k2: fused middle, 2 chunks/iter, hoisted guard ---------------
__global__ __launch_bounds__(256) void k2_mma(const float* __restrict__ w1B,
                                              const float* __restrict__ w2A) {
    __shared__ uint4 sb[4][128];
    __shared__ uint4 sa[4][128];
    __shared__ float sM[RR * RR];

    int tid  = threadIdx.x;
    int warp = tid >> 5, lane = tid & 31;
    int tok0 = blockIdx.x * MT;
    int seg  = blockIdx.y;
    int c0   = seg * NCHUNK_SEG;
    float* z2o = g_z2p + (size_t)seg * TT * RR;

    int e_first = expert_of(tok0);
    int e_last  = expert_of(tok0 + MT - 1);
    bool uni = (e_first == e_last);

    if (!uni) {
        if (tid < MT) {
            int token = tok0 + tid;
            int e = expert_of(token);
            float acc[RR];
#pragma unroll
            for (int r = 0; r < RR; r++) acc[r] = 0.f;
            if (e < EE) {
                float zr[RR];
#pragma unroll
                for (int r = 0; r < RR; r++) zr[r] = g_z1[token * RR + r];
                const float* b1 = w1B + (size_t)e * RR * FFD;
                const float* a2 = w2A + (size_t)e * RR * FFD;
                int f0 = c0 * NC, f1 = f0 + NCHUNK_SEG * NC;
                for (int f = f0; f < f1; f++) {
                    float hv = 0.f;
#pragma unroll
                    for (int r = 0; r < RR; r++)
                        hv = fmaf(zr[r], b1[(size_t)r * FFD + f], hv);
                    float h = gelu_f(hv);
#pragma unroll
                    for (int r = 0; r < RR; r++)
                        acc[r] = fmaf(h, a2[(size_t)r * FFD + f], acc[r]);
                }
            }
#pragma unroll
            for (int r = 0; r < RR; r++) z2o[token * RR + r] = acc[r];
        }
        return;
    }
    if (e_first >= EE) {
        if (tid < MT) {
#pragma unroll
            for (int i = 0; i < 4; i++)
                *(float4*)&z2o[(size_t)(tok0 + tid) * RR + i * 4] =
                    make_float4(0.f, 0.f, 0.f, 0.f);
        }
        return;
    }

    int e = e_first;
    const uint4* cb = (const uint4*)&g_cb1[(size_t)(e * NCHUNK_TOT + c0) * 1024];
    const uint4* ca = (const uint4*)&g_ca2[(size_t)(e * NCHUNK_TOT + c0) * 1024];

    sM[tid] = g_M[e * 256 + tid];

    int mrow = warp * 16 + (lane >> 2);
    int kcol = (lane & 3) * 2;
    uint32_t za[4];
    {
        float2 v00 = *(const float2*)&g_z1[(tok0 + mrow) * RR + kcol];
        float2 v10 = *(const float2*)&g_z1[(tok0 + mrow + 8) * RR + kcol];
        float2 v01 = *(const float2*)&g_z1[(tok0 + mrow) * RR + kcol + 8];
        float2 v11 = *(const float2*)&g_z1[(tok0 + mrow + 8) * RR + kcol + 8];
        za[0] = h2u(__floats2half2_rn(v00.x, v00.y));
        za[1] = h2u(__floats2half2_rn(v10.x, v10.y));
        za[2] = h2u(__floats2half2_rn(v01.x, v01.y));
        za[3] = h2u(__floats2half2_rn(v11.x, v11.y));
    }

    int pred = 1;
    if (tid < MT) {
        float nz = 0.f;
#pragma unroll
        for (int i = 0; i < 4; i++) {
            float4 v = *(const float4*)&g_z1[(size_t)(tok0 + tid) * RR + i * 4];
            nz = fmaf(v.x, v.x, nz); nz = fmaf(v.y, v.y, nz);
            nz = fmaf(v.z, v.z, nz); nz = fmaf(v.w, v.w, nz);
        }
        float mb2 = __int_as_float(g_mbb[e]);
        pred = (nz * mb2 <= 0.49f) ? 1 : 0;
    }
    int allok = __syncthreads_and(pred);

    if (tid < 128) { sb[0][tid] = cb[tid]; sb[1][tid] = cb[128 + tid]; }
    else { sa[0][tid - 128] = ca[tid - 128]; sa[1][tid - 128] = ca[128 + tid - 128]; }
    __syncthreads();

    float zacc[2][4];
#pragma unroll
    for (int j = 0; j < 2; j++)
#pragma unroll
        for (int q = 0; q < 4; q++) zacc[j][q] = 0.f;

    uint32_t foff = (uint32_t)(lane >> 2) * 32 + (uint32_t)(lane & 3) * 8;
    const u64 gc2p = pack2(GC2, GC2);
    const u64 gc1p = pack2(GC1, GC1);
    const u64 gc0p = pack2(GC0, GC0);

    for (int ci = 0; ci < NCHUNK_SEG; ci += 2) {
        int pair = (ci >> 1) & 1;
        bool have_next = (ci + 2 < NCHUNK_SEG);

        uint4 pf0, pf1;
        if (have_next) {
            if (tid < 128) {
                pf0 = cb[(ci + 2) * 128 + tid];
                pf1 = cb[(ci + 3) * 128 + tid];
            } else {
                pf0 = ca[(ci + 2) * 128 + tid - 128];
                pf1 = ca[(ci + 3) * 128 + tid - 128];
            }
        }

#pragma unroll
        for (int h = 0; h < 2; h++) {
            const char* sbp = (const char*)&sb[2 * pair + h][0];
            const char* sap = (const char*)&sa[2 * pair + h][0];

            float c1[8][4];
#pragma unroll
            for (int j = 0; j < 8; j++) {
                uint2 bf = *(const uint2*)(sbp + j * 256 + foff);
                float zero4[4] = {0.f, 0.f, 0.f, 0.f};
                mma16816(c1[j], za, (const uint32_t*)&bf, zero4);
            }

            uint32_t ga[4][4];
#pragma unroll
            for (int j = 0; j < 8; j++) {
#pragma unroll
                for (int q = 0; q < 2; q++) {
                    float x0 = c1[j][2 * q], x1 = c1[j][2 * q + 1];
                    u64 xv = pack2(x0, x1);
                    u64 tv = ffma2(xv, xv, 0ull);
                    u64 qv = ffma2(gc2p, tv, gc1p);
                    qv = ffma2(qv, tv, gc0p);
                    u64 gv = ffma2(tv, qv, 0ull);
                    float2 gf = unpack2(gv);
                    ga[j >> 1][(j & 1) * 2 + q] = h2u(__floats2half2_rn(gf.x, gf.y));
                }
            }
            if (!allok) {
                float tmax = 0.f;
#pragma unroll
                for (int j = 0; j < 8; j++)
#pragma unroll
                    for (int q = 0; q < 4; q++)
                        tmax = fmaxf(tmax, c1[j][q] * c1[j][q]);
                if (tmax > 0.5f) {
#pragma unroll
                    for (int j = 0; j < 8; j++) {
#pragma unroll
                        for (int q = 0; q < 2; q++) {
                            float x0 = c1[j][2 * q], x1 = c1[j][2 * q + 1];
                            float g0 = gelu_f(x0) - 0.5f * x0;
                            float g1 = gelu_f(x1) - 0.5f * x1;
                            ga[j >> 1][(j & 1) * 2 + q] = h2u(__floats2half2_rn(g0, g1));
                        }
                    }
                }
            }

#pragma unroll
            for (int j = 0; j < 2; j++) {
#pragma unroll
                for (int s = 0; s < 4; s++) {
                    uint2 bf = *(const uint2*)(sap + (j * 4 + s) * 256 + foff);
                    mma16816(zacc[j], ga[s], (const uint32_t*)&bf, zacc[j]);
                }
            }
        }

        if (have_next) {
            int op = 2 * (pair ^ 1);
            if (tid < 128) { sb[op][tid] = pf0; sb[op + 1][tid] = pf1; }
            else { sa[op][tid - 128] = pf0; sa[op + 1][tid - 128] = pf1; }
        }
        __syncthreads();
    }

    {
        int t0 = tok0 + mrow, t1 = t0 + 8;
#pragma unroll
        for (int j = 0; j < 2; j++) {
            u64 accq[2];
#pragma unroll
            for (int q = 0; q < 2; q++)
                accq[q] = pack2(zacc[j][q], zacc[j][q + 2]);
            if (seg == 0) {
                float z1a[RR], z1b[RR];
#pragma unroll
                for (int i = 0; i < 4; i++) {
                    float4 v = *(const float4*)&g_z1[(size_t)t0 * RR + i * 4];
                    float4 w = *(const float4*)&g_z1[(size_t)t1 * RR + i * 4];
                    z1a[i * 4 + 0] = v.x; z1a[i * 4 + 1] = v.y;
                    z1a[i * 4 + 2] = v.z; z1a[i * 4 + 3] = v.w;
                    z1b[i * 4 + 0] = w.x; z1b[i * 4 + 1] = w.y;
                    z1b[i * 4 + 2] = w.z; z1b[i * 4 + 3] = w.w;
                }
#pragma unroll
                for (int q = 0; q < 2; q++) {
                    int r2 = 8 * j + kcol + q;
                    u64 acc = accq[q];
#pragma unroll
                    for (int r1 = 0; r1 < RR; r1++) {
                        float m = sM[r1 * RR + r2];
                        acc = ffma2(pack2(z1a[r1], z1b[r1]), pack2(m, m), acc);
                    }
                    accq[q] = acc;
                }
            }
            float2 a0 = unpack2(accq[0]), a1 = unpack2(accq[1]);
            *(float2*)&z2o[(size_t)t0 * RR + 8 * j + kcol] = make_float2(a0.x, a1.x);
            *(float2*)&z2o[(size_t)t1 * RR + 8 * j + kcol] = make_float2(a0.y, a1.y);
        }
    }
}

// ---------------- k3: out = (sum_seg z2p) @ B2 (fp32, coalesced) ---------------
__global__ __launch_bounds__(256) void k3_out(const float* __restrict__ w2B,
                                              float* __restrict__ out) {
    int tok0 = blockIdx.x * 32;
    int c4   = blockIdx.y * 256 + threadIdx.x;
    __shared__ float zs[32 * RR];
    __shared__ int se[32];
    for (int i = threadIdx.x; i < 32 * RR; i += 256) {
        float s = 0.f;
#pragma unroll
        for (int g = 0; g < NSEG; g++)
            s += g_z2p[(size_t)g * TT * RR + (size_t)tok0 * RR + i];
        zs[i] = s;
    }
    if (threadIdx.x < 32) se[threadIdx.x] = expert_of(tok0 + threadIdx.x);
    __syncthreads();

    int ecur = -1;
    u64 bp[RR * 2];
#pragma unroll 1
    for (int t = 0; t < 32; t++) {
        int e = se[t];
        if (e != ecur) {
            ecur = e;
            int ee = (e < EE) ? e : 0;
#pragma unroll
            for (int r = 0; r < RR; r++) {
                float4 b = *(const float4*)&w2B[(size_t)(ee * RR + r) * HH + c4 * 4];
                bp[r * 2]     = pack2(b.x, b.y);
                bp[r * 2 + 1] = pack2(b.z, b.w);
            }
        }
        u64 accA = 0ull, accB = 0ull;
#pragma unroll
        for (int r = 0; r < RR; r++) {
            float zv = zs[t * RR + r];
            u64 z2v = pack2(zv, zv);
            accA = ffma2(z2v, bp[r * 2], accA);
            accB = ffma2(z2v, bp[r * 2 + 1], accB);
        }
        float2 ra = unpack2(accA), rb = unpack2(accB);
        float4 o = make_float4(ra.x, ra.y, rb.x, rb.y);
        *(float4*)&out[(size_t)(tok0 + t) * HH + c4 * 4] = o;
    }
}

// ---------------- launch --------------------------------------------------------
extern "C" void kernel_launch(void* const* d_in, const int* in_sizes, int n_in,
                              void* d_out, int out_size) {
    const float* x   = (const float*)d_in[0];
    const void*  tpe = (const void*)d_in[1];
    const float* w1A = (const float*)d_in[2];
    const float* w1B = (const float*)d_in[3];
    const float* w2A = (const float*)d_in[4];
    const float* w2B = (const float*)d_in[5];
    float* out = (float*)d_out;

    k_prep<<<EE * NCHUNK_TOT + EE * RR, 256>>>(w1B, w2A, tpe);

    k1_z1<<<TT / K1_TOK, 256>>>(x, w1A);

    dim3 g2(TT / MT, NSEG);
    k2_mma<<<g2, 256>>>(w1B, w2A);

    dim3 g3(TT / 32, HH / 1024);
    k3_out<<<g3, 256>>>(w2B, out);
}